// round 1
// baseline (speedup 1.0000x reference)
#include <cuda_runtime.h>
#include <cstdint>

// ProbSparse (Informer) attention, B=4 L=2048 H=8 D=64, sample_k=n_top=40.
// Reshape in reference is flat-reinterpret: treat Q/K/V as [32][2048][64].
// Output: out[((b*L + l)*H + h)*D + d] = context[bh][l][d].

#define NB   4
#define NH   8
#define NBH  32
#define NL   2048
#define ND   64
#define SK   40
#define NT   40
#define NCH  16       // number of l-chunks
#define LC   128      // chunk length

// JAX threefry path: 1 = partitionable (modern default), 0 = original.
#define PARTITIONABLE 1

#define NEG_MAX (-3.402823466e38f)

// ------------------------- scratch (device globals; no allocs) ---------------
__device__ int   g_index[NL*SK];
__device__ float g_M[NBH*NL];
__device__ int   g_top[NBH*NT];
__device__ float g_tilesum[NBH*NCH*ND];
__device__ float g_pmax[NBH*NCH*NT];
__device__ float g_psum[NBH*NCH*NT];
__device__ float g_pV[NBH*NCH*NT*ND];

// ------------------------- threefry-2x32 (20 rounds) -------------------------
__host__ __device__ __forceinline__ void tf2x32(unsigned k0, unsigned k1,
                                                unsigned x0, unsigned x1,
                                                unsigned& o0, unsigned& o1) {
  unsigned ks2 = k0 ^ k1 ^ 0x1BD11BDAu;
  unsigned ks[3] = {k0, k1, ks2};
  const int R0[4] = {13,15,26,6}, R1[4] = {17,29,16,24};
  x0 += k0; x1 += k1;
  #pragma unroll
  for (int i = 0; i < 5; i++) {
    #pragma unroll
    for (int j = 0; j < 4; j++) {
      int r = (i & 1) ? R1[j] : R0[j];
      x0 += x1;
      x1 = (x1 << r) | (x1 >> (32 - r));
      x1 ^= x0;
    }
    x0 += ks[(i+1)%3];
    x1 += ks[(i+2)%3] + (unsigned)(i+1);
  }
  o0 = x0; o1 = x1;
}

// K0: generate index_sample (randint with power-of-two span -> bits & 2047)
__global__ void k0_idx(unsigned kk0, unsigned kk1) {
  int i = blockIdx.x * blockDim.x + threadIdx.x;
  if (i >= NL*SK) return;
  unsigned o0, o1, w;
#if PARTITIONABLE
  tf2x32(kk0, kk1, 0u, (unsigned)i, o0, o1);
  w = o0 ^ o1;
#else
  const unsigned half = (NL*SK)/2;
  unsigned lo = (i < (int)half) ? (unsigned)i : (unsigned)(i - half);
  tf2x32(kk0, kk1, lo, lo + half, o0, o1);
  w = (i < (int)half) ? o0 : o1;
#endif
  g_index[i] = (int)(w & (unsigned)(NL - 1));
}

// K1: M[bh][q] = max_s QK - sum_s QK / 2048. Warp handles 2 queries
// (16 lanes x float4 each).
__global__ void __launch_bounds__(256) k1_M(const float* __restrict__ Q,
                                            const float* __restrict__ K) {
  int wid  = threadIdx.x >> 5, lane = threadIdx.x & 31;
  int gw   = blockIdx.x * 8 + wid;        // 32768 warps
  int bh   = gw >> 10;
  int qp   = gw & 1023;
  int q    = qp * 2 + (lane >> 4);
  int d4   = lane & 15;
  const float4 qv = *(const float4*)(Q + ((size_t)bh*NL + q)*ND + d4*4);
  const float* Kb = K + (size_t)bh*NL*ND;
  const int* ip = g_index + q*SK;
  float mx = NEG_MAX, sm = 0.f;
  for (int s = 0; s < SK; s++) {
    int id = __ldg(ip + s);
    const float4 kv = *(const float4*)(Kb + (size_t)id*ND + d4*4);
    float pp = qv.x*kv.x + qv.y*kv.y + qv.z*kv.z + qv.w*kv.w;
    #pragma unroll
    for (int o = 8; o; o >>= 1) pp += __shfl_xor_sync(0xffffffffu, pp, o);
    mx = fmaxf(mx, pp);
    sm += pp;
  }
  if (d4 == 0) g_M[bh*NL + q] = mx - sm * (1.0f/2048.0f);
}

// K2: top-40 per bh via iterative argmax extraction (smaller index wins ties).
__global__ void __launch_bounds__(256) k2_topk() {
  __shared__ float m[NL];
  __shared__ float wv[8];
  __shared__ int   wi[8];
  int bh = blockIdx.x, tid = threadIdx.x;
  for (int i = tid; i < NL; i += 256) m[i] = g_M[bh*NL + i];
  __syncthreads();
  for (int t = 0; t < NT; t++) {
    float bv = NEG_MAX; int bi = 0x7fffffff;
    for (int i = tid; i < NL; i += 256) {
      float v = m[i];
      if (v > bv || (v == bv && i < bi)) { bv = v; bi = i; }
    }
    #pragma unroll
    for (int o = 16; o; o >>= 1) {
      float ov = __shfl_xor_sync(0xffffffffu, bv, o);
      int   oi = __shfl_xor_sync(0xffffffffu, bi, o);
      if (ov > bv || (ov == bv && oi < bi)) { bv = ov; bi = oi; }
    }
    if ((tid & 31) == 0) { wv[tid>>5] = bv; wi[tid>>5] = bi; }
    __syncthreads();
    if (tid == 0) {
      #pragma unroll
      for (int k = 1; k < 8; k++)
        if (wv[k] > bv || (wv[k] == bv && wi[k] < bi)) { bv = wv[k]; bi = wi[k]; }
      g_top[bh*NT + t] = bi;
      m[bi] = NEG_MAX;
    }
    __syncthreads();
  }
}

// K3a: per-tile column sums of V (tile = 128 rows)
__global__ void k3a_tilesum(const float* __restrict__ V) {
  int bh = blockIdx.x >> 4, t = blockIdx.x & 15;
  int d = threadIdx.x;    // 64 threads
  const float* Vb = V + (size_t)bh*NL*ND + (size_t)t*LC*ND;
  float s = 0.f;
  #pragma unroll 8
  for (int r = 0; r < LC; r++) s += Vb[r*ND + d];
  g_tilesum[(bh*NCH + t)*ND + d] = s;
}

// K3b: context[l] = 0.5*((l+1)*V[l] + inclusive_cumsum(V)[l]); write ALL rows
// (transposed). Selected rows are overwritten later by K5.
__global__ void k3b_context(const float* __restrict__ V, float* __restrict__ out) {
  int bh = blockIdx.x >> 4, t = blockIdx.x & 15;
  int d = threadIdx.x;    // 64 threads
  int b = bh >> 3, h = bh & 7;
  float run = 0.f;
  for (int tt = 0; tt < t; tt++) run += g_tilesum[(bh*NCH + tt)*ND + d];
  const float* Vb = V + (size_t)bh*NL*ND;
  #pragma unroll 4
  for (int r = 0; r < LC; r++) {
    int l = t*LC + r;
    float v = Vb[(size_t)l*ND + d];
    run += v;
    out[(((size_t)b*NL + l)*NH + h)*ND + d] = 0.5f * ((float)(l+1)*v + run);
  }
}

// K4: split-K scores + partial softmax + partial attn@V per (bh, chunk)
#define QC_PITCH 68
#define QS_OFF   (LC*QC_PITCH)          // 8704
#define KS_OFF   (QS_OFF + NT*ND)       // +2560
#define SC_OFF   (KS_OFF + NT*ND)       // +2560
#define SM_FLOATS (SC_OFF + NT*LC)      // 18944 floats = 75776 B

__global__ void __launch_bounds__(256) k4_scores(const float* __restrict__ Q,
                                                 const float* __restrict__ K,
                                                 const float* __restrict__ V) {
  extern __shared__ float sm[];
  __shared__ int pos[NT];
  int tid = threadIdx.x;
  int bh = blockIdx.x >> 4;
  int c  = blockIdx.x & 15;
  const float* Qb = Q + (size_t)bh*NL*ND;
  const float* Kb = K + (size_t)bh*NL*ND;
  const float* Vb = V + (size_t)bh*NL*ND;

  if (tid < NT) pos[tid] = g_top[bh*NT + tid];
  __syncthreads();

  for (int idx = tid; idx < NT*ND; idx += 256) {
    int u = idx >> 6, e = idx & 63;
    int p = pos[u];
    sm[QS_OFF + idx] = Qb[(size_t)p*ND + e];
    sm[KS_OFF + idx] = Kb[(size_t)p*ND + e];
  }
  int l0 = c * LC;
  for (int idx = tid; idx < LC*ND; idx += 256) {
    int r = idx >> 6, e = idx & 63;
    sm[r*QC_PITCH + e] = Qb[(size_t)(l0 + r)*ND + e];
  }
  int lr = tid & 127;
  float4 kreg[16];
  {
    const float4* kr = (const float4*)(Kb + (size_t)(l0 + lr)*ND);
    #pragma unroll
    for (int e = 0; e < 16; e++) kreg[e] = kr[e];
  }
  __syncthreads();

  // Phase B: scores. Thread owns row lr; group g covers 20 u each.
  int g = tid >> 7;
  const float4* Qrow = (const float4*)(sm + lr*QC_PITCH);
  int l = l0 + lr;
  for (int u = g*20; u < g*20 + 20; u++) {
    const float4* Qs4 = (const float4*)(sm + QS_OFF + u*ND);
    const float4* Ks4 = (const float4*)(sm + KS_OFF + u*ND);
    float d1 = 0.f, d2 = 0.f;
    #pragma unroll
    for (int e = 0; e < 16; e++) {
      float4 a = Qs4[e], bb = kreg[e];
      d1 = fmaf(a.x,bb.x, fmaf(a.y,bb.y, fmaf(a.z,bb.z, fmaf(a.w,bb.w, d1))));
      float4 p = Qrow[e], qk = Ks4[e];
      d2 = fmaf(p.x,qk.x, fmaf(p.y,qk.y, fmaf(p.z,qk.z, fmaf(p.w,qk.w, d2))));
    }
    float s = 0.0625f * (d1 + d2);          // 0.5 * (d1+d2) / sqrt(64)
    if (l > pos[u]) s = -1.0e9f;            // causal mask, matches reference
    sm[SC_OFF + u*LC + lr] = s;
  }
  __syncthreads();

  // Phase C: per-u chunk max / exp / sum (warp per u, strided over 8 warps)
  int w = tid >> 5, lane = tid & 31;
  for (int u = w; u < NT; u += 8) {
    float* row = sm + SC_OFF + u*LC;
    float v0 = row[lane], v1 = row[lane+32], v2 = row[lane+64], v3 = row[lane+96];
    float mx = fmaxf(fmaxf(v0, v1), fmaxf(v2, v3));
    #pragma unroll
    for (int o = 16; o; o >>= 1) mx = fmaxf(mx, __shfl_xor_sync(0xffffffffu, mx, o));
    v0 = __expf(v0 - mx); v1 = __expf(v1 - mx);
    v2 = __expf(v2 - mx); v3 = __expf(v3 - mx);
    row[lane] = v0; row[lane+32] = v1; row[lane+64] = v2; row[lane+96] = v3;
    float ss = v0 + v1 + v2 + v3;
    #pragma unroll
    for (int o = 16; o; o >>= 1) ss += __shfl_xor_sync(0xffffffffu, ss, o);
    if (lane == 0) {
      g_pmax[(bh*NCH + c)*NT + u] = mx;
      g_psum[(bh*NCH + c)*NT + u] = ss;
    }
  }
  __syncthreads();

  // Phase D: pV[u][d] = sum_lr exp_score[u][lr] * V[l0+lr][d]
  const float4* V4 = (const float4*)(Vb + (size_t)l0*ND);
  for (int idx = tid; idx < NT*16; idx += 256) {
    int u = idx >> 4, d4 = idx & 15;
    const float* wrow = sm + SC_OFF + u*LC;
    float4 acc = make_float4(0.f, 0.f, 0.f, 0.f);
    #pragma unroll 4
    for (int r = 0; r < LC; r++) {
      float ww = wrow[r];
      float4 v = V4[r*16 + d4];
      acc.x = fmaf(ww, v.x, acc.x); acc.y = fmaf(ww, v.y, acc.y);
      acc.z = fmaf(ww, v.z, acc.z); acc.w = fmaf(ww, v.w, acc.w);
    }
    ((float4*)(g_pV + ((size_t)(bh*NCH + c)*NT + u)*ND))[d4] = acc;
  }
}

// K5: combine 16 chunk-partials per (bh,u); overwrite selected output rows.
__global__ void __launch_bounds__(256) k5_combine(const float* __restrict__ V,
                                                  float* __restrict__ out) {
  int gw = (blockIdx.x*256 + threadIdx.x) >> 5;   // 1280 warps exactly
  int lane = threadIdx.x & 31;
  int bh = gw / NT, u = gw - bh*NT;
  int p = g_top[bh*NT + u];
  float pm = NEG_MAX, ps = 0.f;
  if (lane < NCH) {
    pm = g_pmax[(bh*NCH + lane)*NT + u];
    ps = g_psum[(bh*NCH + lane)*NT + u];
  }
  float gm = pm;
  #pragma unroll
  for (int o = 16; o; o >>= 1) gm = fmaxf(gm, __shfl_xor_sync(0xffffffffu, gm, o));
  float fac = (lane < NCH) ? __expf(pm - gm) : 0.f;
  float den = fac * ps;
  #pragma unroll
  for (int o = 16; o; o >>= 1) den += __shfl_xor_sync(0xffffffffu, den, o);
  float acc0 = 0.f, acc1 = 0.f;
  #pragma unroll
  for (int ch = 0; ch < NCH; ch++) {
    float fc = __shfl_sync(0xffffffffu, fac, ch);
    const float* pv = g_pV + ((size_t)(bh*NCH + ch)*NT + u)*ND;
    acc0 = fmaf(fc, pv[lane],      acc0);
    acc1 = fmaf(fc, pv[lane + 32], acc1);
  }
  float inv = 1.0f / den;
  const float* vrow = V + ((size_t)bh*NL + p)*ND;
  int b = bh >> 3, h = bh & 7;
  float* orow = out + (((size_t)b*NL + p)*NH + h)*ND;
  orow[lane]      = 0.5f * (vrow[lane]      + acc0*inv);
  orow[lane + 32] = 0.5f * (vrow[lane + 32] + acc1*inv);
}

extern "C" void kernel_launch(void* const* d_in, const int* in_sizes, int n_in,
                              void* d_out, int out_size) {
  const float* Q = (const float*)d_in[0];
  const float* K = (const float*)d_in[1];
  const float* V = (const float*)d_in[2];
  float* out = (float*)d_out;

  // Derive the randint "lower bits" key (second split of key(42)) on host.
  unsigned kk0, kk1;
#if PARTITIONABLE
  unsigned o0, o1;
  tf2x32(0u, 42u, 0u, 1u, o0, o1);   // 64-bit iota element 1 -> (hi=0, lo=1)
  kk0 = o0; kk1 = o1;
#else
  unsigned a0, a1, b0, b1;
  tf2x32(0u, 42u, 0u, 2u, a0, a1);
  tf2x32(0u, 42u, 1u, 3u, b0, b1);
  kk0 = a1; kk1 = b1;                // second row of reshape(2,2)
#endif

  cudaFuncSetAttribute(k4_scores, cudaFuncAttributeMaxDynamicSharedMemorySize,
                       SM_FLOATS * 4);

  k0_idx<<<(NL*SK + 255)/256, 256>>>(kk0, kk1);
  k1_M<<<4096, 256>>>(Q, K);
  k2_topk<<<NBH, 256>>>();
  k3a_tilesum<<<NBH*NCH, 64>>>(V);
  k3b_context<<<NBH*NCH, 64>>>(V, out);
  k4_scores<<<NBH*NCH, 256, SM_FLOATS*4>>>(Q, K, V);
  k5_combine<<<160, 256>>>(V, out);
}

// round 2
// speedup vs baseline: 1.0273x; 1.0273x over previous
#include <cuda_runtime.h>
#include <cstdint>

// ProbSparse (Informer) attention, B=4 L=2048 H=8 D=64, sample_k=n_top=40.
// Q/K/V are flat-reinterpreted [32][2048][64]; output is [B,L,H,D] transpose.

#define NB   4
#define NH   8
#define NBH  32
#define NL   2048
#define ND   64
#define SK   40
#define NT   40
#define NCH  16       // l-chunks for k4/k5
#define LC   128      // chunk length
#define ST   32       // cumsum subtile rows
#define NST  64       // subtiles per bh

#define PARTITIONABLE 1
#define NEG_MAX (-3.402823466e38f)

// ------------------------- scratch (device globals) --------------------------
__device__ int   g_index[NL*SK];
__device__ float g_M[NBH*NL];
__device__ int   g_top[NBH*NT];
__device__ float g_ss[NBH*NST*ND];
__device__ float g_sp[NBH*NST*ND];
__device__ float g_pmax[NBH*NCH*NT];
__device__ float g_psum[NBH*NCH*NT];
__device__ float g_pV[NBH*NCH*NT*ND];

// ------------------------- threefry-2x32 (20 rounds) -------------------------
__host__ __device__ __forceinline__ void tf2x32(unsigned k0, unsigned k1,
                                                unsigned x0, unsigned x1,
                                                unsigned& o0, unsigned& o1) {
  unsigned ks2 = k0 ^ k1 ^ 0x1BD11BDAu;
  unsigned ks[3] = {k0, k1, ks2};
  const int R0[4] = {13,15,26,6}, R1[4] = {17,29,16,24};
  x0 += k0; x1 += k1;
  #pragma unroll
  for (int i = 0; i < 5; i++) {
    #pragma unroll
    for (int j = 0; j < 4; j++) {
      int r = (i & 1) ? R1[j] : R0[j];
      x0 += x1;
      x1 = (x1 << r) | (x1 >> (32 - r));
      x1 ^= x0;
    }
    x0 += ks[(i+1)%3];
    x1 += ks[(i+2)%3] + (unsigned)(i+1);
  }
  o0 = x0; o1 = x1;
}

// K0: index_sample (randint, power-of-two span -> bits & 2047)
__global__ void k0_idx(unsigned kk0, unsigned kk1) {
  int i = blockIdx.x * blockDim.x + threadIdx.x;
  if (i >= NL*SK) return;
  unsigned o0, o1, w;
#if PARTITIONABLE
  tf2x32(kk0, kk1, 0u, (unsigned)i, o0, o1);
  w = o0 ^ o1;
#else
  const unsigned half = (NL*SK)/2;
  unsigned lo = (i < (int)half) ? (unsigned)i : (unsigned)(i - half);
  tf2x32(kk0, kk1, lo, lo + half, o0, o1);
  w = (i < (int)half) ? o0 : o1;
#endif
  g_index[i] = (int)(w & (unsigned)(NL - 1));
}

// K1: M[bh][q] = max_s QK - sum_s QK / 2048.
// Warp = 2 queries (16 lanes x float4). Unroll 8 samples for MLP.
__global__ void __launch_bounds__(256) k1_M(const float* __restrict__ Q,
                                            const float* __restrict__ K) {
  int wid  = threadIdx.x >> 5, lane = threadIdx.x & 31;
  int gw   = blockIdx.x * 8 + wid;
  int bh   = gw >> 10;
  int q    = (gw & 1023) * 2 + (lane >> 4);
  int d4   = lane & 15;
  const float4 qv = __ldg((const float4*)(Q + ((size_t)bh*NL + q)*ND) + d4);
  const float* Kb = K + (size_t)bh*NL*ND;
  const int* __restrict__ ip = g_index + q*SK;
  float mx = NEG_MAX, sm = 0.f;
  #pragma unroll 1
  for (int s0 = 0; s0 < SK; s0 += 8) {
    float pp[8];
    #pragma unroll
    for (int j = 0; j < 8; j++) {
      int id = __ldg(ip + s0 + j);
      const float4 kv = __ldg((const float4*)(Kb + (size_t)id*ND) + d4);
      pp[j] = qv.x*kv.x + qv.y*kv.y + qv.z*kv.z + qv.w*kv.w;
    }
    #pragma unroll
    for (int o = 8; o; o >>= 1) {
      #pragma unroll
      for (int j = 0; j < 8; j++)
        pp[j] += __shfl_xor_sync(0xffffffffu, pp[j], o);
    }
    #pragma unroll
    for (int j = 0; j < 8; j++) { mx = fmaxf(mx, pp[j]); sm += pp[j]; }
  }
  if (d4 == 0) g_M[bh*NL + q] = mx - sm * (1.0f/2048.0f);
}

// K2: top-40 per bh via iterative argmax (smaller index wins ties).
__global__ void __launch_bounds__(256) k2_topk() {
  __shared__ float m[NL];
  __shared__ float wv[8];
  __shared__ int   wi[8];
  int bh = blockIdx.x, tid = threadIdx.x;
  for (int i = tid; i < NL; i += 256) m[i] = g_M[bh*NL + i];
  __syncthreads();
  for (int t = 0; t < NT; t++) {
    float bv = NEG_MAX; int bi = 0x7fffffff;
    for (int i = tid; i < NL; i += 256) {
      float v = m[i];
      if (v > bv || (v == bv && i < bi)) { bv = v; bi = i; }
    }
    #pragma unroll
    for (int o = 16; o; o >>= 1) {
      float ov = __shfl_xor_sync(0xffffffffu, bv, o);
      int   oi = __shfl_xor_sync(0xffffffffu, bi, o);
      if (ov > bv || (ov == bv && oi < bi)) { bv = ov; bi = oi; }
    }
    if ((tid & 31) == 0) { wv[tid>>5] = bv; wi[tid>>5] = bi; }
    __syncthreads();
    if (tid == 0) {
      #pragma unroll
      for (int k = 1; k < 8; k++)
        if (wv[k] > bv || (wv[k] == bv && wi[k] < bi)) { bv = wv[k]; bi = wi[k]; }
      g_top[bh*NT + t] = bi;
      m[bi] = NEG_MAX;
    }
    __syncthreads();
  }
}

// K3a: 32-row subtile column sums. Block = 4 subtiles x 64 dims.
__global__ void __launch_bounds__(256) k3a_tilesum(const float* __restrict__ V) {
  int bh = blockIdx.x >> 4;
  int st = (blockIdx.x & 15) * 4 + (threadIdx.x >> 6);
  int d  = threadIdx.x & 63;
  const float* Vb = V + (size_t)bh*NL*ND + (size_t)st*ST*ND + d;
  float s = 0.f;
  #pragma unroll 8
  for (int r = 0; r < ST; r++) s += __ldg(Vb + r*ND);
  g_ss[(bh*NST + st)*ND + d] = s;
}

// K3p: exclusive prefix over the 64 subtile sums per (bh, d).
__global__ void __launch_bounds__(64) k3p_prefix() {
  int bh = blockIdx.x, d = threadIdx.x;
  float run = 0.f;
  for (int st = 0; st < NST; st++) {
    float t = g_ss[(bh*NST + st)*ND + d];
    g_sp[(bh*NST + st)*ND + d] = run;
    run += t;
  }
}

// K3b: context = 0.5*((l+1)*V[l] + cumsum(V)[l]) for all rows (transposed out).
__global__ void __launch_bounds__(256) k3b_context(const float* __restrict__ V,
                                                   float* __restrict__ out) {
  int bh = blockIdx.x >> 4;
  int st = (blockIdx.x & 15) * 4 + (threadIdx.x >> 6);
  int d  = threadIdx.x & 63;
  int b = bh >> 3, h = bh & 7;
  float run = g_sp[(bh*NST + st)*ND + d];
  const float* Vb = V + (size_t)bh*NL*ND;
  #pragma unroll 4
  for (int r = 0; r < ST; r++) {
    int l = st*ST + r;
    float v = __ldg(Vb + (size_t)l*ND + d);
    run += v;
    out[(((size_t)b*NL + l)*NH + h)*ND + d] = 0.5f * ((float)(l+1)*v + run);
  }
}

// K4: per (bh, chunk) scores + partial softmax + partial attn@V.
// All smem reads in the dot phases are 128-thread broadcasts; the per-thread
// K row / Q row live in registers.
__global__ void __launch_bounds__(256) k4_scores(const float* __restrict__ Q,
                                                 const float* __restrict__ K,
                                                 const float* __restrict__ V) {
  __shared__ float sQs[NT*ND];
  __shared__ float sKs[NT*ND];
  __shared__ float sSc[NT*LC];
  __shared__ int   pos[NT];
  int tid = threadIdx.x;
  int bh = blockIdx.x >> 4;
  int c  = blockIdx.x & 15;
  const float* Qb = Q + (size_t)bh*NL*ND;
  const float* Kb = K + (size_t)bh*NL*ND;
  const float* Vb = V + (size_t)bh*NL*ND;

  if (tid < NT) pos[tid] = g_top[bh*NT + tid];
  __syncthreads();
  for (int idx = tid; idx < NT*ND; idx += 256) {
    int u = idx >> 6, e = idx & 63;
    int p = pos[u];
    sQs[idx] = __ldg(Qb + (size_t)p*ND + e);
    sKs[idx] = __ldg(Kb + (size_t)p*ND + e);
  }
  int l0 = c * LC;
  int lr = tid & 127;
  int g  = tid >> 7;             // two groups of 128 threads, 20 u each
  int l  = l0 + lr;

  // Phase B1: d1[u][lr] = dot(Q_sel[u], K[l]);  K row in registers.
  float4 rreg[16];
  {
    const float4* kr = (const float4*)(Kb + (size_t)l*ND);
    #pragma unroll
    for (int e = 0; e < 16; e++) rreg[e] = __ldg(kr + e);
  }
  __syncthreads();
  #pragma unroll 2
  for (int t = 0; t < 20; t++) {
    int u = g*20 + t;
    const float4* Qs4 = (const float4*)(sQs + u*ND);
    float a0 = 0.f, a1 = 0.f;
    #pragma unroll
    for (int e = 0; e < 16; e += 2) {
      float4 x = Qs4[e],   y = rreg[e];
      a0 = fmaf(x.x,y.x, fmaf(x.y,y.y, fmaf(x.z,y.z, fmaf(x.w,y.w, a0))));
      float4 x2 = Qs4[e+1], y2 = rreg[e+1];
      a1 = fmaf(x2.x,y2.x, fmaf(x2.y,y2.y, fmaf(x2.z,y2.z, fmaf(x2.w,y2.w, a1))));
    }
    sSc[u*LC + lr] = a0 + a1;
  }
  // Phase B2: d2[u][lr] = dot(Q[l], K_sel[u]); Q row now in registers.
  {
    const float4* qr = (const float4*)(Qb + (size_t)l*ND);
    #pragma unroll
    for (int e = 0; e < 16; e++) rreg[e] = __ldg(qr + e);
  }
  #pragma unroll 2
  for (int t = 0; t < 20; t++) {
    int u = g*20 + t;
    const float4* Ks4 = (const float4*)(sKs + u*ND);
    float a0 = 0.f, a1 = 0.f;
    #pragma unroll
    for (int e = 0; e < 16; e += 2) {
      float4 x = Ks4[e],   y = rreg[e];
      a0 = fmaf(x.x,y.x, fmaf(x.y,y.y, fmaf(x.z,y.z, fmaf(x.w,y.w, a0))));
      float4 x2 = Ks4[e+1], y2 = rreg[e+1];
      a1 = fmaf(x2.x,y2.x, fmaf(x2.y,y2.y, fmaf(x2.z,y2.z, fmaf(x2.w,y2.w, a1))));
    }
    float s = 0.0625f * (sSc[u*LC + lr] + a0 + a1);  // 0.5*(d1+d2)/sqrt(64)
    if (l > pos[u]) s = -1.0e9f;
    sSc[u*LC + lr] = s;
  }
  __syncthreads();

  // Phase C: per-u chunk max / exp / sum (warp per u, strided over 8 warps)
  int w = tid >> 5, lane = tid & 31;
  for (int u = w; u < NT; u += 8) {
    float* row = sSc + u*LC;
    float v0 = row[lane], v1 = row[lane+32], v2 = row[lane+64], v3 = row[lane+96];
    float mx = fmaxf(fmaxf(v0, v1), fmaxf(v2, v3));
    #pragma unroll
    for (int o = 16; o; o >>= 1) mx = fmaxf(mx, __shfl_xor_sync(0xffffffffu, mx, o));
    v0 = __expf(v0 - mx); v1 = __expf(v1 - mx);
    v2 = __expf(v2 - mx); v3 = __expf(v3 - mx);
    row[lane] = v0; row[lane+32] = v1; row[lane+64] = v2; row[lane+96] = v3;
    float ss = v0 + v1 + v2 + v3;
    #pragma unroll
    for (int o = 16; o; o >>= 1) ss += __shfl_xor_sync(0xffffffffu, ss, o);
    if (lane == 0) {
      g_pmax[(bh*NCH + c)*NT + u] = mx;
      g_psum[(bh*NCH + c)*NT + u] = ss;
    }
  }
  __syncthreads();

  // Phase D: pV[u][d] = sum_r w[u][r] * V[l0+r][d]
  const float4* V4 = (const float4*)(Vb + (size_t)l0*ND);
  for (int idx = tid; idx < NT*16; idx += 256) {
    int u = idx >> 4, d4 = idx & 15;
    const float* wrow = sSc + u*LC;
    float4 acc = make_float4(0.f, 0.f, 0.f, 0.f);
    #pragma unroll 4
    for (int r = 0; r < LC; r++) {
      float ww = wrow[r];
      float4 v = __ldg(V4 + r*16 + d4);
      acc.x = fmaf(ww, v.x, acc.x); acc.y = fmaf(ww, v.y, acc.y);
      acc.z = fmaf(ww, v.z, acc.z); acc.w = fmaf(ww, v.w, acc.w);
    }
    ((float4*)(g_pV + ((size_t)(bh*NCH + c)*NT + u)*ND))[d4] = acc;
  }
}

// K5: merge 16 chunk-partials per (bh,u); overwrite selected rows.
__global__ void __launch_bounds__(256) k5_combine(const float* __restrict__ V,
                                                  float* __restrict__ out) {
  int gw = (blockIdx.x*256 + threadIdx.x) >> 5;   // 1280 warps
  int lane = threadIdx.x & 31;
  int bh = gw / NT, u = gw - bh*NT;
  int p = g_top[bh*NT + u];
  float pm = NEG_MAX, ps = 0.f;
  if (lane < NCH) {
    pm = g_pmax[(bh*NCH + lane)*NT + u];
    ps = g_psum[(bh*NCH + lane)*NT + u];
  }
  float gm = pm;
  #pragma unroll
  for (int o = 16; o; o >>= 1) gm = fmaxf(gm, __shfl_xor_sync(0xffffffffu, gm, o));
  float fac = (lane < NCH) ? __expf(pm - gm) : 0.f;
  float den = fac * ps;
  #pragma unroll
  for (int o = 16; o; o >>= 1) den += __shfl_xor_sync(0xffffffffu, den, o);
  float acc0 = 0.f, acc1 = 0.f;
  #pragma unroll
  for (int ch = 0; ch < NCH; ch++) {
    float fc = __shfl_sync(0xffffffffu, fac, ch);
    const float* pv = g_pV + ((size_t)(bh*NCH + ch)*NT + u)*ND;
    acc0 = fmaf(fc, pv[lane],      acc0);
    acc1 = fmaf(fc, pv[lane + 32], acc1);
  }
  float inv = 1.0f / den;
  const float* vrow = V + ((size_t)bh*NL + p)*ND;
  int b = bh >> 3, h = bh & 7;
  float* orow = out + (((size_t)b*NL + p)*NH + h)*ND;
  orow[lane]      = 0.5f * (vrow[lane]      + acc0*inv);
  orow[lane + 32] = 0.5f * (vrow[lane + 32] + acc1*inv);
}

extern "C" void kernel_launch(void* const* d_in, const int* in_sizes, int n_in,
                              void* d_out, int out_size) {
  const float* Q = (const float*)d_in[0];
  const float* K = (const float*)d_in[1];
  const float* V = (const float*)d_in[2];
  float* out = (float*)d_out;

  unsigned kk0, kk1;
#if PARTITIONABLE
  unsigned o0, o1;
  tf2x32(0u, 42u, 0u, 1u, o0, o1);
  kk0 = o0; kk1 = o1;
#else
  unsigned a0, a1, b0, b1;
  tf2x32(0u, 42u, 0u, 2u, a0, a1);
  tf2x32(0u, 42u, 1u, 3u, b0, b1);
  kk0 = a1; kk1 = b1;
#endif

  k0_idx<<<(NL*SK + 255)/256, 256>>>(kk0, kk1);
  k1_M<<<4096, 256>>>(Q, K);
  k3a_tilesum<<<NBH*NCH, 256>>>(V);
  k3p_prefix<<<NBH, 64>>>();
  k2_topk<<<NBH, 256>>>();
  k3b_context<<<NBH*NCH, 256>>>(V, out);
  k4_scores<<<NBH*NCH, 256>>>(Q, K, V);
  k5_combine<<<160, 256>>>(V, out);
}

// round 3
// speedup vs baseline: 1.0794x; 1.0507x over previous
#include <cuda_runtime.h>
#include <cstdint>

// ProbSparse (Informer) attention, B=4 L=2048 H=8 D=64, sample_k=n_top=40.
// Q/K/V are flat-reinterpreted [32][2048][64]; output is [B,L,H,D] transpose.

#define NB   4
#define NH   8
#define NBH  32
#define NL   2048
#define ND   64
#define SK   40
#define NT   40
#define NCH  16       // l-chunks for k4/k5
#define LC   128      // chunk length
#define ST   32       // cumsum subtile rows
#define NST  64       // subtiles per bh

#define PARTITIONABLE 1
#define NEG_MAX (-3.402823466e38f)

// ------------------------- scratch (device globals) --------------------------
__device__ int   g_index[NL*SK];
__device__ float g_M[NBH*NL];
__device__ int   g_top[NBH*NT];
__device__ float g_ss[NBH*NST*ND];
__device__ float g_sp[NBH*NST*ND];
__device__ float g_pmax[NBH*NCH*NT];
__device__ float g_psum[NBH*NCH*NT];
__device__ float g_pV[NBH*NCH*NT*ND];

// ------------------------- threefry-2x32 (20 rounds) -------------------------
__host__ __device__ __forceinline__ void tf2x32(unsigned k0, unsigned k1,
                                                unsigned x0, unsigned x1,
                                                unsigned& o0, unsigned& o1) {
  unsigned ks2 = k0 ^ k1 ^ 0x1BD11BDAu;
  unsigned ks[3] = {k0, k1, ks2};
  const int R0[4] = {13,15,26,6}, R1[4] = {17,29,16,24};
  x0 += k0; x1 += k1;
  #pragma unroll
  for (int i = 0; i < 5; i++) {
    #pragma unroll
    for (int j = 0; j < 4; j++) {
      int r = (i & 1) ? R1[j] : R0[j];
      x0 += x1;
      x1 = (x1 << r) | (x1 >> (32 - r));
      x1 ^= x0;
    }
    x0 += ks[(i+1)%3];
    x1 += ks[(i+2)%3] + (unsigned)(i+1);
  }
  o0 = x0; o1 = x1;
}

// K0: index_sample (randint, power-of-two span -> bits & 2047)
__global__ void k0_idx(unsigned kk0, unsigned kk1) {
  int i = blockIdx.x * blockDim.x + threadIdx.x;
  if (i >= NL*SK) return;
  unsigned o0, o1, w;
#if PARTITIONABLE
  tf2x32(kk0, kk1, 0u, (unsigned)i, o0, o1);
  w = o0 ^ o1;
#else
  const unsigned half = (NL*SK)/2;
  unsigned lo = (i < (int)half) ? (unsigned)i : (unsigned)(i - half);
  tf2x32(kk0, kk1, lo, lo + half, o0, o1);
  w = (i < (int)half) ? o0 : o1;
#endif
  g_index[i] = (int)(w & (unsigned)(NL - 1));
}

// K1: M[bh][q] = max_s QK - sum_s QK / 2048.
// Warp = 2 queries (16 lanes x float4). Unroll 8 samples for MLP.
__global__ void __launch_bounds__(256) k1_M(const float* __restrict__ Q,
                                            const float* __restrict__ K) {
  int wid  = threadIdx.x >> 5, lane = threadIdx.x & 31;
  int gw   = blockIdx.x * 8 + wid;
  int bh   = gw >> 10;
  int q    = (gw & 1023) * 2 + (lane >> 4);
  int d4   = lane & 15;
  const float4 qv = __ldg((const float4*)(Q + ((size_t)bh*NL + q)*ND) + d4);
  const float* Kb = K + (size_t)bh*NL*ND;
  const int* __restrict__ ip = g_index + q*SK;
  float mx = NEG_MAX, sm = 0.f;
  #pragma unroll 1
  for (int s0 = 0; s0 < SK; s0 += 8) {
    float pp[8];
    #pragma unroll
    for (int j = 0; j < 8; j++) {
      int id = __ldg(ip + s0 + j);
      const float4 kv = __ldg((const float4*)(Kb + (size_t)id*ND) + d4);
      pp[j] = qv.x*kv.x + qv.y*kv.y + qv.z*kv.z + qv.w*kv.w;
    }
    #pragma unroll
    for (int o = 8; o; o >>= 1) {
      #pragma unroll
      for (int j = 0; j < 8; j++)
        pp[j] += __shfl_xor_sync(0xffffffffu, pp[j], o);
    }
    #pragma unroll
    for (int j = 0; j < 8; j++) { mx = fmaxf(mx, pp[j]); sm += pp[j]; }
  }
  if (d4 == 0) g_M[bh*NL + q] = mx - sm * (1.0f/2048.0f);
}

// K2: top-40 per bh via iterative argmax (smaller index wins ties).
__global__ void __launch_bounds__(256) k2_topk() {
  __shared__ float m[NL];
  __shared__ float wv[8];
  __shared__ int   wi[8];
  int bh = blockIdx.x, tid = threadIdx.x;
  for (int i = tid; i < NL; i += 256) m[i] = g_M[bh*NL + i];
  __syncthreads();
  for (int t = 0; t < NT; t++) {
    float bv = NEG_MAX; int bi = 0x7fffffff;
    for (int i = tid; i < NL; i += 256) {
      float v = m[i];
      if (v > bv || (v == bv && i < bi)) { bv = v; bi = i; }
    }
    #pragma unroll
    for (int o = 16; o; o >>= 1) {
      float ov = __shfl_xor_sync(0xffffffffu, bv, o);
      int   oi = __shfl_xor_sync(0xffffffffu, bi, o);
      if (ov > bv || (ov == bv && oi < bi)) { bv = ov; bi = oi; }
    }
    if ((tid & 31) == 0) { wv[tid>>5] = bv; wi[tid>>5] = bi; }
    __syncthreads();
    if (tid == 0) {
      #pragma unroll
      for (int k = 1; k < 8; k++)
        if (wv[k] > bv || (wv[k] == bv && wi[k] < bi)) { bv = wv[k]; bi = wi[k]; }
      g_top[bh*NT + t] = bi;
      m[bi] = NEG_MAX;
    }
    __syncthreads();
  }
}

// K3a: 32-row subtile column sums. Block = 4 subtiles x 64 dims.
__global__ void __launch_bounds__(256) k3a_tilesum(const float* __restrict__ V) {
  int bh = blockIdx.x >> 4;
  int st = (blockIdx.x & 15) * 4 + (threadIdx.x >> 6);
  int d  = threadIdx.x & 63;
  const float* Vb = V + (size_t)bh*NL*ND + (size_t)st*ST*ND + d;
  float s = 0.f;
  #pragma unroll 8
  for (int r = 0; r < ST; r++) s += __ldg(Vb + r*ND);
  g_ss[(bh*NST + st)*ND + d] = s;
}

// K3p: exclusive prefix over the 64 subtile sums per (bh, d).
__global__ void __launch_bounds__(64) k3p_prefix() {
  int bh = blockIdx.x, d = threadIdx.x;
  float run = 0.f;
  for (int st = 0; st < NST; st++) {
    float t = g_ss[(bh*NST + st)*ND + d];
    g_sp[(bh*NST + st)*ND + d] = run;
    run += t;
  }
}

// K3b: context = 0.5*((l+1)*V[l] + cumsum(V)[l]) for all rows (transposed out).
__global__ void __launch_bounds__(256) k3b_context(const float* __restrict__ V,
                                                   float* __restrict__ out) {
  int bh = blockIdx.x >> 4;
  int st = (blockIdx.x & 15) * 4 + (threadIdx.x >> 6);
  int d  = threadIdx.x & 63;
  int b = bh >> 3, h = bh & 7;
  float run = g_sp[(bh*NST + st)*ND + d];
  const float* Vb = V + (size_t)bh*NL*ND;
  #pragma unroll 4
  for (int r = 0; r < ST; r++) {
    int l = st*ST + r;
    float v = __ldg(Vb + (size_t)l*ND + d);
    run += v;
    out[(((size_t)b*NL + l)*NH + h)*ND + d] = 0.5f * ((float)(l+1)*v + run);
  }
}

// K4: per (bh, chunk) scores + partial softmax + partial attn@V.
// All smem reads in the dot phases are 128-thread broadcasts; the per-thread
// K row / Q row live in registers.
__global__ void __launch_bounds__(256) k4_scores(const float* __restrict__ Q,
                                                 const float* __restrict__ K,
                                                 const float* __restrict__ V) {
  __shared__ float sQs[NT*ND];
  __shared__ float sKs[NT*ND];
  __shared__ float sSc[NT*LC];
  __shared__ int   pos[NT];
  int tid = threadIdx.x;
  int bh = blockIdx.x >> 4;
  int c  = blockIdx.x & 15;
  const float* Qb = Q + (size_t)bh*NL*ND;
  const float* Kb = K + (size_t)bh*NL*ND;
  const float* Vb = V + (size_t)bh*NL*ND;

  if (tid < NT) pos[tid] = g_top[bh*NT + tid];
  __syncthreads();
  for (int idx = tid; idx < NT*ND; idx += 256) {
    int u = idx >> 6, e = idx & 63;
    int p = pos[u];
    sQs[idx] = __ldg(Qb + (size_t)p*ND + e);
    sKs[idx] = __ldg(Kb + (size_t)p*ND + e);
  }
  int l0 = c * LC;
  int lr = tid & 127;
  int g  = tid >> 7;             // two groups of 128 threads, 20 u each
  int l  = l0 + lr;

  // Phase B1: d1[u][lr] = dot(Q_sel[u], K[l]);  K row in registers.
  float4 rreg[16];
  {
    const float4* kr = (const float4*)(Kb + (size_t)l*ND);
    #pragma unroll
    for (int e = 0; e < 16; e++) rreg[e] = __ldg(kr + e);
  }
  __syncthreads();
  #pragma unroll 2
  for (int t = 0; t < 20; t++) {
    int u = g*20 + t;
    const float4* Qs4 = (const float4*)(sQs + u*ND);
    float a0 = 0.f, a1 = 0.f;
    #pragma unroll
    for (int e = 0; e < 16; e += 2) {
      float4 x = Qs4[e],   y = rreg[e];
      a0 = fmaf(x.x,y.x, fmaf(x.y,y.y, fmaf(x.z,y.z, fmaf(x.w,y.w, a0))));
      float4 x2 = Qs4[e+1], y2 = rreg[e+1];
      a1 = fmaf(x2.x,y2.x, fmaf(x2.y,y2.y, fmaf(x2.z,y2.z, fmaf(x2.w,y2.w, a1))));
    }
    sSc[u*LC + lr] = a0 + a1;
  }
  // Phase B2: d2[u][lr] = dot(Q[l], K_sel[u]); Q row now in registers.
  {
    const float4* qr = (const float4*)(Qb + (size_t)l*ND);
    #pragma unroll
    for (int e = 0; e < 16; e++) rreg[e] = __ldg(qr + e);
  }
  #pragma unroll 2
  for (int t = 0; t < 20; t++) {
    int u = g*20 + t;
    const float4* Ks4 = (const float4*)(sKs + u*ND);
    float a0 = 0.f, a1 = 0.f;
    #pragma unroll
    for (int e = 0; e < 16; e += 2) {
      float4 x = Ks4[e],   y = rreg[e];
      a0 = fmaf(x.x,y.x, fmaf(x.y,y.y, fmaf(x.z,y.z, fmaf(x.w,y.w, a0))));
      float4 x2 = Ks4[e+1], y2 = rreg[e+1];
      a1 = fmaf(x2.x,y2.x, fmaf(x2.y,y2.y, fmaf(x2.z,y2.z, fmaf(x2.w,y2.w, a1))));
    }
    float s = 0.0625f * (sSc[u*LC + lr] + a0 + a1);  // 0.5*(d1+d2)/sqrt(64)
    if (l > pos[u]) s = -1.0e9f;
    sSc[u*LC + lr] = s;
  }
  __syncthreads();

  // Phase C: per-u chunk max / exp / sum (warp per u, strided over 8 warps)
  int w = tid >> 5, lane = tid & 31;
  for (int u = w; u < NT; u += 8) {
    float* row = sSc + u*LC;
    float v0 = row[lane], v1 = row[lane+32], v2 = row[lane+64], v3 = row[lane+96];
    float mx = fmaxf(fmaxf(v0, v1), fmaxf(v2, v3));
    #pragma unroll
    for (int o = 16; o; o >>= 1) mx = fmaxf(mx, __shfl_xor_sync(0xffffffffu, mx, o));
    v0 = __expf(v0 - mx); v1 = __expf(v1 - mx);
    v2 = __expf(v2 - mx); v3 = __expf(v3 - mx);
    row[lane] = v0; row[lane+32] = v1; row[lane+64] = v2; row[lane+96] = v3;
    float ss = v0 + v1 + v2 + v3;
    #pragma unroll
    for (int o = 16; o; o >>= 1) ss += __shfl_xor_sync(0xffffffffu, ss, o);
    if (lane == 0) {
      g_pmax[(bh*NCH + c)*NT + u] = mx;
      g_psum[(bh*NCH + c)*NT + u] = ss;
    }
  }
  __syncthreads();

  // Phase D: pV[u][d] = sum_r w[u][r] * V[l0+r][d]
  const float4* V4 = (const float4*)(Vb + (size_t)l0*ND);
  for (int idx = tid; idx < NT*16; idx += 256) {
    int u = idx >> 4, d4 = idx & 15;
    const float* wrow = sSc + u*LC;
    float4 acc = make_float4(0.f, 0.f, 0.f, 0.f);
    #pragma unroll 4
    for (int r = 0; r < LC; r++) {
      float ww = wrow[r];
      float4 v = __ldg(V4 + r*16 + d4);
      acc.x = fmaf(ww, v.x, acc.x); acc.y = fmaf(ww, v.y, acc.y);
      acc.z = fmaf(ww, v.z, acc.z); acc.w = fmaf(ww, v.w, acc.w);
    }
    ((float4*)(g_pV + ((size_t)(bh*NCH + c)*NT + u)*ND))[d4] = acc;
  }
}

// K5: merge 16 chunk-partials per (bh,u); overwrite selected rows.
__global__ void __launch_bounds__(256) k5_combine(const float* __restrict__ V,
                                                  float* __restrict__ out) {
  int gw = (blockIdx.x*256 + threadIdx.x) >> 5;   // 1280 warps
  int lane = threadIdx.x & 31;
  int bh = gw / NT, u = gw - bh*NT;
  int p = g_top[bh*NT + u];
  float pm = NEG_MAX, ps = 0.f;
  if (lane < NCH) {
    pm = g_pmax[(bh*NCH + lane)*NT + u];
    ps = g_psum[(bh*NCH + lane)*NT + u];
  }
  float gm = pm;
  #pragma unroll
  for (int o = 16; o; o >>= 1) gm = fmaxf(gm, __shfl_xor_sync(0xffffffffu, gm, o));
  float fac = (lane < NCH) ? __expf(pm - gm) : 0.f;
  float den = fac * ps;
  #pragma unroll
  for (int o = 16; o; o >>= 1) den += __shfl_xor_sync(0xffffffffu, den, o);
  float acc0 = 0.f, acc1 = 0.f;
  #pragma unroll
  for (int ch = 0; ch < NCH; ch++) {
    float fc = __shfl_sync(0xffffffffu, fac, ch);
    const float* pv = g_pV + ((size_t)(bh*NCH + ch)*NT + u)*ND;
    acc0 = fmaf(fc, pv[lane],      acc0);
    acc1 = fmaf(fc, pv[lane + 32], acc1);
  }
  float inv = 1.0f / den;
  const float* vrow = V + ((size_t)bh*NL + p)*ND;
  int b = bh >> 3, h = bh & 7;
  float* orow = out + (((size_t)b*NL + p)*NH + h)*ND;
  orow[lane]      = 0.5f * (vrow[lane]      + acc0*inv);
  orow[lane + 32] = 0.5f * (vrow[lane + 32] + acc1*inv);
}

extern "C" void kernel_launch(void* const* d_in, const int* in_sizes, int n_in,
                              void* d_out, int out_size) {
  const float* Q = (const float*)d_in[0];
  const float* K = (const float*)d_in[1];
  const float* V = (const float*)d_in[2];
  float* out = (float*)d_out;

  unsigned kk0, kk1;
#if PARTITIONABLE
  unsigned o0, o1;
  tf2x32(0u, 42u, 0u, 1u, o0, o1);
  kk0 = o0; kk1 = o1;
#else
  unsigned a0, a1, b0, b1;
  tf2x32(0u, 42u, 0u, 2u, a0, a1);
  tf2x32(0u, 42u, 1u, 3u, b0, b1);
  kk0 = a1; kk1 = b1;
#endif

  k0_idx<<<(NL*SK + 255)/256, 256>>>(kk0, kk1);
  k1_M<<<4096, 256>>>(Q, K);
  k3a_tilesum<<<NBH*NCH, 256>>>(V);
  k3p_prefix<<<NBH, 64>>>();
  k2_topk<<<NBH, 256>>>();
  k3b_context<<<NBH*NCH, 256>>>(V, out);
  k4_scores<<<NBH*NCH, 256>>>(Q, K, V);
  k5_combine<<<160, 256>>>(V, out);
}

// round 4
// speedup vs baseline: 1.1235x; 1.0409x over previous
#include <cuda_runtime.h>
#include <cstdint>

// ProbSparse (Informer) attention, B=4 L=2048 H=8 D=64, sample_k=n_top=40.
// Q/K/V are flat-reinterpreted [32][2048][64]; output is [B,L,H,D] transpose.

#define NB   4
#define NH   8
#define NBH  32
#define NL   2048
#define ND   64
#define SK   40
#define NT   40
#define NCH  16       // l-chunks for k4/k5
#define LC   128      // chunk length
#define ST   32       // cumsum subtile rows
#define NST  64       // subtiles per bh

#define PARTITIONABLE 1
#define NEG_MAX (-3.402823466e38f)

// ------------------------- scratch (device globals) --------------------------
__device__ int   g_index[NL*SK];
__device__ float g_M[NBH*NL];
__device__ int   g_top[NBH*NT];
__device__ float g_ss[NBH*NST*ND];
__device__ float g_pmax[NBH*NCH*NT];
__device__ float g_psum[NBH*NCH*NT];
__device__ float g_pV[NBH*NCH*NT*ND];

// ------------------------- threefry-2x32 (20 rounds) -------------------------
__host__ __device__ __forceinline__ void tf2x32(unsigned k0, unsigned k1,
                                                unsigned x0, unsigned x1,
                                                unsigned& o0, unsigned& o1) {
  unsigned ks2 = k0 ^ k1 ^ 0x1BD11BDAu;
  unsigned ks[3] = {k0, k1, ks2};
  const int R0[4] = {13,15,26,6}, R1[4] = {17,29,16,24};
  x0 += k0; x1 += k1;
  #pragma unroll
  for (int i = 0; i < 5; i++) {
    #pragma unroll
    for (int j = 0; j < 4; j++) {
      int r = (i & 1) ? R1[j] : R0[j];
      x0 += x1;
      x1 = (x1 << r) | (x1 >> (32 - r));
      x1 ^= x0;
    }
    x0 += ks[(i+1)%3];
    x1 += ks[(i+2)%3] + (unsigned)(i+1);
  }
  o0 = x0; o1 = x1;
}

// K0: index_sample (randint, power-of-two span -> bits & 2047)
__global__ void k0_idx(unsigned kk0, unsigned kk1) {
  int i = blockIdx.x * blockDim.x + threadIdx.x;
  if (i >= NL*SK) return;
  unsigned o0, o1, w;
#if PARTITIONABLE
  tf2x32(kk0, kk1, 0u, (unsigned)i, o0, o1);
  w = o0 ^ o1;
#else
  const unsigned half = (NL*SK)/2;
  unsigned lo = (i < (int)half) ? (unsigned)i : (unsigned)(i - half);
  tf2x32(kk0, kk1, lo, lo + half, o0, o1);
  w = (i < (int)half) ? o0 : o1;
#endif
  g_index[i] = (int)(w & (unsigned)(NL - 1));
}

// K1: M[bh][q] = max_s QK - sum_s QK / 2048.
// Warp = 2 queries (16 lanes x float4). 8-sample unroll for MLP.
__global__ void __launch_bounds__(256) k1_M(const float* __restrict__ Q,
                                            const float* __restrict__ K) {
  int wid  = threadIdx.x >> 5, lane = threadIdx.x & 31;
  int gw   = blockIdx.x * 8 + wid;
  int bh   = gw >> 10;
  int q    = (gw & 1023) * 2 + (lane >> 4);
  int d4   = lane & 15;
  const float4 qv = __ldg((const float4*)(Q + ((size_t)bh*NL + q)*ND) + d4);
  const float* Kb = K + (size_t)bh*NL*ND;
  const int* __restrict__ ip = g_index + q*SK;
  float mx = NEG_MAX, sm = 0.f;
  #pragma unroll 1
  for (int s0 = 0; s0 < SK; s0 += 8) {
    int id[8];
    #pragma unroll
    for (int j = 0; j < 8; j++) id[j] = __ldg(ip + s0 + j);
    float pp[8];
    #pragma unroll
    for (int j = 0; j < 8; j++) {
      const float4 kv = __ldg((const float4*)(Kb + (size_t)id[j]*ND) + d4);
      pp[j] = qv.x*kv.x + qv.y*kv.y + qv.z*kv.z + qv.w*kv.w;
    }
    #pragma unroll
    for (int o = 8; o; o >>= 1) {
      #pragma unroll
      for (int j = 0; j < 8; j++)
        pp[j] += __shfl_xor_sync(0xffffffffu, pp[j], o);
    }
    #pragma unroll
    for (int j = 0; j < 8; j++) { mx = fmaxf(mx, pp[j]); sm += pp[j]; }
  }
  if (d4 == 0) g_M[bh*NL + q] = mx - sm * (1.0f/2048.0f);
}

// K2: top-40 per bh via iterative argmax (smaller index wins ties).
__global__ void __launch_bounds__(256) k2_topk() {
  __shared__ float m[NL];
  __shared__ float wv[8];
  __shared__ int   wi[8];
  int bh = blockIdx.x, tid = threadIdx.x;
  for (int i = tid; i < NL; i += 256) m[i] = g_M[bh*NL + i];
  __syncthreads();
  for (int t = 0; t < NT; t++) {
    float bv = NEG_MAX; int bi = 0x7fffffff;
    for (int i = tid; i < NL; i += 256) {
      float v = m[i];
      if (v > bv || (v == bv && i < bi)) { bv = v; bi = i; }
    }
    #pragma unroll
    for (int o = 16; o; o >>= 1) {
      float ov = __shfl_xor_sync(0xffffffffu, bv, o);
      int   oi = __shfl_xor_sync(0xffffffffu, bi, o);
      if (ov > bv || (ov == bv && oi < bi)) { bv = ov; bi = oi; }
    }
    if ((tid & 31) == 0) { wv[tid>>5] = bv; wi[tid>>5] = bi; }
    __syncthreads();
    if (tid == 0) {
      #pragma unroll
      for (int k = 1; k < 8; k++)
        if (wv[k] > bv || (wv[k] == bv && wi[k] < bi)) { bv = wv[k]; bi = wi[k]; }
      g_top[bh*NT + t] = bi;
      m[bi] = NEG_MAX;
    }
    __syncthreads();
  }
}

// K3a: 32-row subtile column sums. Block = 4 subtiles x 64 dims.
__global__ void __launch_bounds__(256) k3a_tilesum(const float* __restrict__ V) {
  int bh = blockIdx.x >> 4;
  int st = (blockIdx.x & 15) * 4 + (threadIdx.x >> 6);
  int d  = threadIdx.x & 63;
  const float* Vb = V + (size_t)bh*NL*ND + (size_t)st*ST*ND + d;
  float s = 0.f;
  #pragma unroll 8
  for (int r = 0; r < ST; r++) s += __ldg(Vb + r*ND);
  g_ss[(bh*NST + st)*ND + d] = s;
}

// K3b: context = 0.5*((l+1)*V[l] + cumsum(V)[l]) for all rows (transposed out).
// Prefix over subtile sums computed in-block (smem Hillis-Steele) — no k3p.
__global__ void __launch_bounds__(256) k3b_context(const float* __restrict__ V,
                                                   float* __restrict__ out) {
  __shared__ float s[NST*ND];        // 16 KB: inclusive prefix of subtile sums
  int tid = threadIdx.x;
  int bh = blockIdx.x >> 4;
  int c  = blockIdx.x & 15;
  for (int i = tid; i < NST*ND; i += 256) s[i] = g_ss[bh*NST*ND + i];
  __syncthreads();
  #pragma unroll
  for (int off = 1; off < NST; off <<= 1) {
    float add[16];
    #pragma unroll
    for (int j = 0; j < 16; j++) {
      int idx = tid + j*256;
      int st = idx >> 6, d = idx & 63;
      add[j] = (st >= off) ? s[(st-off)*ND + d] : 0.f;
    }
    __syncthreads();
    #pragma unroll
    for (int j = 0; j < 16; j++) s[tid + j*256] += add[j];
    __syncthreads();
  }
  int stl = tid >> 6;
  int d   = tid & 63;
  int st  = c*4 + stl;
  int b = bh >> 3, h = bh & 7;
  float run = (st > 0) ? s[(st-1)*ND + d] : 0.f;
  const float* Vb = V + (size_t)bh*NL*ND;
  #pragma unroll 4
  for (int r = 0; r < ST; r++) {
    int l = st*ST + r;
    float v = __ldg(Vb + (size_t)l*ND + d);
    run += v;
    out[(((size_t)b*NL + l)*NH + h)*ND + d] = 0.5f * ((float)(l+1)*v + run);
  }
}

// K4: per (bh, chunk) scores + partial softmax + partial attn@V.
__global__ void __launch_bounds__(256) k4_scores(const float* __restrict__ Q,
                                                 const float* __restrict__ K,
                                                 const float* __restrict__ V) {
  __shared__ float sQs[NT*ND];
  __shared__ float sKs[NT*ND];
  __shared__ float sSc[NT*LC];
  __shared__ int   pos[NT];
  int tid = threadIdx.x;
  int bh = blockIdx.x >> 4;
  int c  = blockIdx.x & 15;
  const float* Qb = Q + (size_t)bh*NL*ND;
  const float* Kb = K + (size_t)bh*NL*ND;
  const float* Vb = V + (size_t)bh*NL*ND;

  if (tid < NT) pos[tid] = g_top[bh*NT + tid];
  __syncthreads();
  for (int idx = tid; idx < NT*ND; idx += 256) {
    int u = idx >> 6, e = idx & 63;
    int p = pos[u];
    sQs[idx] = __ldg(Qb + (size_t)p*ND + e);
    sKs[idx] = __ldg(Kb + (size_t)p*ND + e);
  }
  int l0 = c * LC;
  int lr = tid & 127;
  int g  = tid >> 7;
  int l  = l0 + lr;

  // Phase B1: d1[u][lr] = dot(Q_sel[u], K[l]);  K row in registers.
  float4 rreg[16];
  {
    const float4* kr = (const float4*)(Kb + (size_t)l*ND);
    #pragma unroll
    for (int e = 0; e < 16; e++) rreg[e] = __ldg(kr + e);
  }
  __syncthreads();
  #pragma unroll 2
  for (int t = 0; t < 20; t++) {
    int u = g*20 + t;
    const float4* Qs4 = (const float4*)(sQs + u*ND);
    float a0 = 0.f, a1 = 0.f;
    #pragma unroll
    for (int e = 0; e < 16; e += 2) {
      float4 x = Qs4[e],   y = rreg[e];
      a0 = fmaf(x.x,y.x, fmaf(x.y,y.y, fmaf(x.z,y.z, fmaf(x.w,y.w, a0))));
      float4 x2 = Qs4[e+1], y2 = rreg[e+1];
      a1 = fmaf(x2.x,y2.x, fmaf(x2.y,y2.y, fmaf(x2.z,y2.z, fmaf(x2.w,y2.w, a1))));
    }
    sSc[u*LC + lr] = a0 + a1;
  }
  // Phase B2: d2[u][lr] = dot(Q[l], K_sel[u]); Q row in registers.
  {
    const float4* qr = (const float4*)(Qb + (size_t)l*ND);
    #pragma unroll
    for (int e = 0; e < 16; e++) rreg[e] = __ldg(qr + e);
  }
  #pragma unroll 2
  for (int t = 0; t < 20; t++) {
    int u = g*20 + t;
    const float4* Ks4 = (const float4*)(sKs + u*ND);
    float a0 = 0.f, a1 = 0.f;
    #pragma unroll
    for (int e = 0; e < 16; e += 2) {
      float4 x = Ks4[e],   y = rreg[e];
      a0 = fmaf(x.x,y.x, fmaf(x.y,y.y, fmaf(x.z,y.z, fmaf(x.w,y.w, a0))));
      float4 x2 = Ks4[e+1], y2 = rreg[e+1];
      a1 = fmaf(x2.x,y2.x, fmaf(x2.y,y2.y, fmaf(x2.z,y2.z, fmaf(x2.w,y2.w, a1))));
    }
    float s = 0.0625f * (sSc[u*LC + lr] + a0 + a1);  // 0.5*(d1+d2)/sqrt(64)
    if (l > pos[u]) s = -1.0e9f;
    sSc[u*LC + lr] = s;
  }
  __syncthreads();

  // Phase C: per-u chunk max / exp / sum (warp per u, strided over 8 warps)
  int w = tid >> 5, lane = tid & 31;
  for (int u = w; u < NT; u += 8) {
    float* row = sSc + u*LC;
    float v0 = row[lane], v1 = row[lane+32], v2 = row[lane+64], v3 = row[lane+96];
    float mx = fmaxf(fmaxf(v0, v1), fmaxf(v2, v3));
    #pragma unroll
    for (int o = 16; o; o >>= 1) mx = fmaxf(mx, __shfl_xor_sync(0xffffffffu, mx, o));
    v0 = __expf(v0 - mx); v1 = __expf(v1 - mx);
    v2 = __expf(v2 - mx); v3 = __expf(v3 - mx);
    row[lane] = v0; row[lane+32] = v1; row[lane+64] = v2; row[lane+96] = v3;
    float ss = v0 + v1 + v2 + v3;
    #pragma unroll
    for (int o = 16; o; o >>= 1) ss += __shfl_xor_sync(0xffffffffu, ss, o);
    if (lane == 0) {
      g_pmax[(bh*NCH + c)*NT + u] = mx;
      g_psum[(bh*NCH + c)*NT + u] = ss;
    }
  }
  __syncthreads();

  // Phase D: pV[u][d] = sum_r w[u][r] * V[l0+r][d]
  const float4* V4 = (const float4*)(Vb + (size_t)l0*ND);
  for (int idx = tid; idx < NT*16; idx += 256) {
    int u = idx >> 4, d4 = idx & 15;
    const float* wrow = sSc + u*LC;
    float4 acc = make_float4(0.f, 0.f, 0.f, 0.f);
    #pragma unroll 4
    for (int r = 0; r < LC; r++) {
      float ww = wrow[r];
      float4 v = __ldg(V4 + r*16 + d4);
      acc.x = fmaf(ww, v.x, acc.x); acc.y = fmaf(ww, v.y, acc.y);
      acc.z = fmaf(ww, v.z, acc.z); acc.w = fmaf(ww, v.w, acc.w);
    }
    ((float4*)(g_pV + ((size_t)(bh*NCH + c)*NT + u)*ND))[d4] = acc;
  }
}

// K5: merge 16 chunk-partials per (bh,u); overwrite selected rows.
__global__ void __launch_bounds__(256) k5_combine(const float* __restrict__ V,
                                                  float* __restrict__ out) {
  int gw = (blockIdx.x*256 + threadIdx.x) >> 5;   // 1280 warps
  int lane = threadIdx.x & 31;
  int bh = gw / NT, u = gw - bh*NT;
  int p = g_top[bh*NT + u];
  float pm = NEG_MAX, ps = 0.f;
  if (lane < NCH) {
    pm = g_pmax[(bh*NCH + lane)*NT + u];
    ps = g_psum[(bh*NCH + lane)*NT + u];
  }
  float gm = pm;
  #pragma unroll
  for (int o = 16; o; o >>= 1) gm = fmaxf(gm, __shfl_xor_sync(0xffffffffu, gm, o));
  float fac = (lane < NCH) ? __expf(pm - gm) : 0.f;
  float den = fac * ps;
  #pragma unroll
  for (int o = 16; o; o >>= 1) den += __shfl_xor_sync(0xffffffffu, den, o);
  float acc0 = 0.f, acc1 = 0.f;
  #pragma unroll
  for (int ch = 0; ch < NCH; ch++) {
    float fc = __shfl_sync(0xffffffffu, fac, ch);
    const float* pv = g_pV + ((size_t)(bh*NCH + ch)*NT + u)*ND;
    acc0 = fmaf(fc, pv[lane],      acc0);
    acc1 = fmaf(fc, pv[lane + 32], acc1);
  }
  float inv = 1.0f / den;
  const float* vrow = V + ((size_t)bh*NL + p)*ND;
  int b = bh >> 3, h = bh & 7;
  float* orow = out + (((size_t)b*NL + p)*NH + h)*ND;
  orow[lane]      = 0.5f * (vrow[lane]      + acc0*inv);
  orow[lane + 32] = 0.5f * (vrow[lane + 32] + acc1*inv);
}

extern "C" void kernel_launch(void* const* d_in, const int* in_sizes, int n_in,
                              void* d_out, int out_size) {
  const float* Q = (const float*)d_in[0];
  const float* K = (const float*)d_in[1];
  const float* V = (const float*)d_in[2];
  float* out = (float*)d_out;

  unsigned kk0, kk1;
#if PARTITIONABLE
  unsigned o0, o1;
  tf2x32(0u, 42u, 0u, 1u, o0, o1);
  kk0 = o0; kk1 = o1;
#else
  unsigned a0, a1, b0, b1;
  tf2x32(0u, 42u, 0u, 2u, a0, a1);
  tf2x32(0u, 42u, 1u, 3u, b0, b1);
  kk0 = a1; kk1 = b1;
#endif

  // Side stream for the V-cumsum chain (created once; creation happens on the
  // uncaptured correctness call, reused identically on every call after).
  static cudaStream_t sB = nullptr;
  static cudaEvent_t evF = nullptr, evJ = nullptr;
  if (sB == nullptr) {
    cudaStreamCreateWithFlags(&sB, cudaStreamNonBlocking);
    cudaEventCreateWithFlags(&evF, cudaEventDisableTiming);
    cudaEventCreateWithFlags(&evJ, cudaEventDisableTiming);
  }

  // Fork: k3a/k3b depend only on V.
  cudaEventRecord(evF, 0);
  cudaStreamWaitEvent(sB, evF, 0);
  k3a_tilesum<<<NBH*NCH, 256, 0, sB>>>(V);
  k3b_context<<<NBH*NCH, 256, 0, sB>>>(V, out);
  cudaEventRecord(evJ, sB);

  // Main chain.
  k0_idx<<<(NL*SK + 255)/256, 256>>>(kk0, kk1);
  k1_M<<<4096, 256>>>(Q, K);
  k2_topk<<<NBH, 256>>>();
  k4_scores<<<NBH*NCH, 256>>>(Q, K, V);

  // Join: k5 overwrites selected rows of out (needs k3b and k4).
  cudaStreamWaitEvent(0, evJ, 0);
  k5_combine<<<160, 256>>>(V, out);
}